// round 16
// baseline (speedup 1.0000x reference)
#include <cuda_runtime.h>
#include <cuda_bf16.h>
#include <cstdint>

// BTT layer: B=4096, M1=M2=N1=N2=64, R=4.
//   stage1 (per m2): C[4096x256] = x[:, m2*64:+64] @ W1[m2]   (K=64)
//   stage2 (per n1): y[:, n1*64:+64] = t[n1] @ W2[n1]         (K=256)
// bf16 hi/lo split, 3 combos -> ~6e-6 rel err.
// g_t stores MMA-ready (hi2, lo2) fragment words.
// R16: 8 slabs of 512 b-rows; fused overlap working set (32MB rd + 32MB wr + io)
//      fits L2 (126MB) -> stage2 t reads are L2 hits.

#define NB 4096
#define SLAB 512

__device__ uint4 g_t[16777216];     // 256MB
__device__ uint4 g_w1hi[131072];    // [m2][n=256][k-octet=8] (2MB)
__device__ uint4 g_w1lo[131072];
__device__ uint4 g_w2hi[131072];    // [n1][n2=64][k-octet=32] (2MB)
__device__ uint4 g_w2lo[131072];

__device__ __forceinline__ void fsplit2(float e0, float e1, uint32_t& w_hi, uint32_t& w_lo) {
    asm("cvt.rn.bf16x2.f32 %0, %1, %2;" : "=r"(w_hi) : "f"(e1), "f"(e0));
    float h0 = __uint_as_float(w_hi << 16);
    float h1 = __uint_as_float(w_hi & 0xFFFF0000u);
    float r0 = e0 - h0, r1 = e1 - h1;
    asm("cvt.rn.bf16x2.f32 %0, %1, %2;" : "=r"(w_lo) : "f"(r1), "f"(r0));
}
__device__ __forceinline__ void mma16816(float* c, const uint32_t* a, const uint32_t* b) {
    asm volatile("mma.sync.aligned.m16n8k16.row.col.f32.bf16.bf16.f32 "
        "{%0,%1,%2,%3}, {%4,%5,%6,%7}, {%8,%9}, {%0,%1,%2,%3};"
        : "+f"(c[0]), "+f"(c[1]), "+f"(c[2]), "+f"(c[3])
        : "r"(a[0]), "r"(a[1]), "r"(a[2]), "r"(a[3]), "r"(b[0]), "r"(b[1]));
}
__device__ __forceinline__ void ldsm4(uint32_t* r, uint32_t addr) {
    asm volatile("ldmatrix.sync.aligned.m8n8.x4.shared.b16 {%0,%1,%2,%3}, [%4];"
        : "=r"(r[0]), "=r"(r[1]), "=r"(r[2]), "=r"(r[3]) : "r"(addr));
}

#define RS 144

// ---------------- prep kernels ----------------------------------------------
__global__ void prep_w1_kernel(const float* __restrict__ W1) {
    const int m2 = blockIdx.x, n = threadIdx.x;
    const float* Wm = W1 + (size_t)m2 * 16384;
    #pragma unroll
    for (int j = 0; j < 8; j++) {
        uint32_t h[4], l[4];
        #pragma unroll
        for (int q = 0; q < 4; q++)
            fsplit2(Wm[(8 * j + 2 * q) * 256 + n], Wm[(8 * j + 2 * q + 1) * 256 + n], h[q], l[q]);
        const int idx = (m2 * 256 + n) * 8 + j;
        g_w1hi[idx] = make_uint4(h[0], h[1], h[2], h[3]);
        g_w1lo[idx] = make_uint4(l[0], l[1], l[2], l[3]);
    }
}
__global__ void prep_w2_kernel(const float* __restrict__ W2) {
    const int n1 = blockIdx.x, tid = threadIdx.x;
    const int n2 = tid & 63, kq = tid >> 6;
    const float* Wn = W2 + (size_t)n1 * 16384;
    #pragma unroll
    for (int j = 0; j < 8; j++) {
        const int k0 = kq * 64 + j * 8;
        uint32_t h[4], l[4];
        #pragma unroll
        for (int q = 0; q < 4; q++)
            fsplit2(Wn[(k0 + 2 * q) * 64 + n2], Wn[(k0 + 2 * q + 1) * 64 + n2], h[q], l[q]);
        const int idx = (n1 * 64 + n2) * 32 + kq * 8 + j;
        g_w2hi[idx] = make_uint4(h[0], h[1], h[2], h[3]);
        g_w2lo[idx] = make_uint4(l[0], l[1], l[2], l[3]);
    }
}

// ---------------- stage 1 body: tile 128(b) x 128(n), K=64 ------------------
#define S1_BHI 0
#define S1_BLO 18432
#define S1_SMEM 36864

__device__ __forceinline__ void stage1_body(const float* __restrict__ x, int bslab,
                                            int m2, int by, int nz, char* smem) {
    const uint32_t sb = (uint32_t)__cvta_generic_to_shared(smem);
    const int tid = threadIdx.x, wid = tid >> 5, lane = tid & 31;
    const int b0 = bslab + by * 128, nbase = nz * 128;

    {   // B fill
        const uint4* bh = g_w1hi + (m2 * 256 + nbase) * 8;
        const uint4* bl = g_w1lo + (m2 * 256 + nbase) * 8;
        #pragma unroll
        for (int i = 0; i < 4; i++) {
            const int idx = tid + 256 * i;
            const int row = idx >> 3, q = idx & 7;
            *(uint4*)(smem + S1_BHI + row * RS + q * 16) = bh[idx];
            *(uint4*)(smem + S1_BLO + row * RS + q * 16) = bl[idx];
        }
    }
    __syncthreads();

    const int qr = lane >> 2, qc = lane & 3;
    const uint32_t laneB = (uint32_t)(((lane & 7) + ((lane & 16) ? 8 : 0)) * RS +
                                      ((lane & 8) ? 16 : 0));
    const int row0 = b0 + wid * 16 + qr;
    const float* xr0 = x + (size_t)row0 * 4096 + m2 * 64;
    const float* xr1 = xr0 + (size_t)8 * 4096;

    float acc[16][4];
    #pragma unroll
    for (int nt = 0; nt < 16; nt++)
        #pragma unroll
        for (int r = 0; r < 4; r++) acc[nt][r] = 0.f;

    float2 f[4];
    f[0] = *(const float2*)(xr0 + 2 * qc);
    f[1] = *(const float2*)(xr1 + 2 * qc);
    f[2] = *(const float2*)(xr0 + 2 * qc + 8);
    f[3] = *(const float2*)(xr1 + 2 * qc + 8);

    #pragma unroll
    for (int ks = 0; ks < 4; ks++) {
        float2 nf[4];
        if (ks < 3) {
            const int k0 = (ks + 1) * 16 + 2 * qc;
            nf[0] = *(const float2*)(xr0 + k0);
            nf[1] = *(const float2*)(xr1 + k0);
            nf[2] = *(const float2*)(xr0 + k0 + 8);
            nf[3] = *(const float2*)(xr1 + k0 + 8);
        }
        uint32_t ah[4], al[4];
        fsplit2(f[0].x, f[0].y, ah[0], al[0]);
        fsplit2(f[1].x, f[1].y, ah[1], al[1]);
        fsplit2(f[2].x, f[2].y, ah[2], al[2]);
        fsplit2(f[3].x, f[3].y, ah[3], al[3]);

        #pragma unroll
        for (int h = 0; h < 2; h++) {
            uint32_t b[8][2];
            #pragma unroll
            for (int p = 0; p < 4; p++) {
                uint32_t r[4];
                ldsm4(r, sb + S1_BHI + laneB + (h * 4 + p) * 16 * RS + ks * 32);
                b[2 * p][0] = r[0]; b[2 * p][1] = r[1];
                b[2 * p + 1][0] = r[2]; b[2 * p + 1][1] = r[3];
            }
            #pragma unroll
            for (int nt = 0; nt < 8; nt++) {
                mma16816(acc[h * 8 + nt], ah, b[nt]);
                mma16816(acc[h * 8 + nt], al, b[nt]);
            }
        }
        #pragma unroll
        for (int h = 0; h < 2; h++) {
            uint32_t b[8][2];
            #pragma unroll
            for (int p = 0; p < 4; p++) {
                uint32_t r[4];
                ldsm4(r, sb + S1_BLO + laneB + (h * 4 + p) * 16 * RS + ks * 32);
                b[2 * p][0] = r[0]; b[2 * p][1] = r[1];
                b[2 * p + 1][0] = r[2]; b[2 * p + 1][1] = r[3];
            }
            #pragma unroll
            for (int nt = 0; nt < 8; nt++)
                mma16816(acc[h * 8 + nt], ah, b[nt]);
        }
        if (ks < 3) { f[0] = nf[0]; f[1] = nf[1]; f[2] = nf[2]; f[3] = nf[3]; }
    }

    uint32_t* gt = (uint32_t*)g_t;
    #pragma unroll
    for (int nt = 0; nt < 16; nt++) {
        const int cg = nbase + nt * 8 + qc * 2;
        const size_t base = (((size_t)(cg >> 2) * 64 + m2) * 4096) * 4 + (cg & 3);
        uint32_t whi, wlo;
        fsplit2(acc[nt][0], acc[nt][1], whi, wlo);
        *(uint2*)(gt + base + (size_t)row0 * 4) = make_uint2(whi, wlo);
        fsplit2(acc[nt][2], acc[nt][3], whi, wlo);
        *(uint2*)(gt + base + (size_t)(row0 + 8) * 4) = make_uint2(whi, wlo);
    }
}

// ---------------- stage 2 body: tile 128(b) x 64(n2), K=256 -----------------
#define S2_BHI 0
#define S2_BLO 36864
#define S2_SMEM 73728
#define TA0 0
#define TA1 32
#define TA2 32768
#define TA3 32800
#define TSTEP 65536

__device__ __forceinline__ void stage2_body(float* __restrict__ y, int bslab,
                                            int n1, int by, char* smem) {
    const uint32_t sb = (uint32_t)__cvta_generic_to_shared(smem);
    const int tid = threadIdx.x, wid = tid >> 5, lane = tid & 31;
    const int b0 = bslab + by * 128;

    {   // B fill
        const uint4* bh = g_w2hi + n1 * 2048;
        const uint4* bl = g_w2lo + n1 * 2048;
        #pragma unroll
        for (int i = 0; i < 8; i++) {
            const int idx = tid + 256 * i;
            const int n2 = idx >> 5, w = idx & 31;
            const int chunk = w >> 3, q = w & 7;
            const int dst = chunk * 9216 + n2 * RS + q * 16;
            *(uint4*)(smem + S2_BHI + dst) = bh[idx];
            *(uint4*)(smem + S2_BLO + dst) = bl[idx];
        }
    }
    __syncthreads();

    const int qr = lane >> 2, qc = lane & 3;
    const uint32_t laneB = (uint32_t)(((lane & 7) + ((lane & 16) ? 8 : 0)) * RS +
                                      ((lane & 8) ? 16 : 0));
    const int qch = qc >> 1, rr = (qc & 1) * 2;
    const int row0 = b0 + wid * 16 + qr;

    float acc[8][4];
    #pragma unroll
    for (int nt = 0; nt < 8; nt++)
        #pragma unroll
        for (int r = 0; r < 4; r++) acc[nt][r] = 0.f;

    const uint32_t* tp = (const uint32_t*)g_t + (size_t)n1 * 64 * 16384 +
                         (size_t)qch * 16384 + (size_t)row0 * 4 + rr;

    uint2 cur[4], nx1[4];
    cur[0] = *(const uint2*)(tp + TA0); cur[1] = *(const uint2*)(tp + TA1);
    cur[2] = *(const uint2*)(tp + TA2); cur[3] = *(const uint2*)(tp + TA3);
    tp += TSTEP;
    nx1[0] = *(const uint2*)(tp + TA0); nx1[1] = *(const uint2*)(tp + TA1);
    nx1[2] = *(const uint2*)(tp + TA2); nx1[3] = *(const uint2*)(tp + TA3);

    #pragma unroll
    for (int g = 0; g < 16; g++) {
        uint2 nx2[4];
        if (g < 14) {
            tp += TSTEP;
            nx2[0] = *(const uint2*)(tp + TA0); nx2[1] = *(const uint2*)(tp + TA1);
            nx2[2] = *(const uint2*)(tp + TA2); nx2[3] = *(const uint2*)(tp + TA3);
        }
        uint32_t ah[4] = {cur[0].x, cur[1].x, cur[2].x, cur[3].x};
        uint32_t al[4] = {cur[0].y, cur[1].y, cur[2].y, cur[3].y};

        const int ch = g >> 2, ksl = g & 3;
        uint32_t b[8][2];
        {
            #pragma unroll
            for (int p = 0; p < 4; p++) {
                uint32_t r[4];
                ldsm4(r, sb + S2_BHI + ch * 9216 + laneB + p * 16 * RS + ksl * 32);
                b[2 * p][0] = r[0]; b[2 * p][1] = r[1];
                b[2 * p + 1][0] = r[2]; b[2 * p + 1][1] = r[3];
            }
            #pragma unroll
            for (int nt = 0; nt < 8; nt++) {
                mma16816(acc[nt], ah, b[nt]);
                mma16816(acc[nt], al, b[nt]);
            }
        }
        {
            #pragma unroll
            for (int p = 0; p < 4; p++) {
                uint32_t r[4];
                ldsm4(r, sb + S2_BLO + ch * 9216 + laneB + p * 16 * RS + ksl * 32);
                b[2 * p][0] = r[0]; b[2 * p][1] = r[1];
                b[2 * p + 1][0] = r[2]; b[2 * p + 1][1] = r[3];
            }
            #pragma unroll
            for (int nt = 0; nt < 8; nt++)
                mma16816(acc[nt], ah, b[nt]);
        }
        #pragma unroll
        for (int i = 0; i < 4; i++) { cur[i] = nx1[i]; }
        if (g < 14) {
            #pragma unroll
            for (int i = 0; i < 4; i++) { nx1[i] = nx2[i]; }
        }
    }

    #pragma unroll
    for (int nt = 0; nt < 8; nt++) {
        const int col = n1 * 64 + nt * 8 + qc * 2;
        *(float2*)(y + (size_t)row0 * 4096 + col) = make_float2(acc[nt][0], acc[nt][1]);
        *(float2*)(y + (size_t)(row0 + 8) * 4096 + col) = make_float2(acc[nt][2], acc[nt][3]);
    }
}

// ---------------- kernels ----------------------------------------------------
__global__ void __launch_bounds__(256, 2)
stage1_kernel(const float* __restrict__ x, int bslab) {
    extern __shared__ char smem[];
    stage1_body(x, bslab, blockIdx.x, blockIdx.y, blockIdx.z, smem);
}
__global__ void __launch_bounds__(256, 2)
stage2_kernel(float* __restrict__ y, int bslab) {
    extern __shared__ char smem[];
    stage2_body(y, bslab, blockIdx.x, blockIdx.y, smem);
}
// fused (512-row slabs): blocks [0,256) = stage2(slab_s2): n1 64 x by 4;
//                        blocks [256,768) = stage1(slab_s1): m2 64 x by 4 x nz 2
__global__ void __launch_bounds__(256, 2)
fused_kernel(const float* __restrict__ x, float* __restrict__ y,
             int slab_s2, int slab_s1) {
    extern __shared__ char smem[];
    const int bx = blockIdx.x;
    if (bx < 256) {
        stage2_body(y, slab_s2, bx & 63, bx >> 6, smem);
    } else {
        const int v = bx - 256;
        stage1_body(x, slab_s1, v & 63, (v >> 6) & 3, v >> 8, smem);
    }
}

// ---------------------------------------------------------------------------
extern "C" void kernel_launch(void* const* d_in, const int* in_sizes, int n_in,
                              void* d_out, int out_size) {
    const float* x  = (const float*)d_in[0];
    const float* W1 = (const float*)d_in[1];
    const float* W2 = (const float*)d_in[2];
    float* y = (float*)d_out;

    cudaFuncSetAttribute(stage1_kernel, cudaFuncAttributeMaxDynamicSharedMemorySize, S1_SMEM);
    cudaFuncSetAttribute(stage2_kernel, cudaFuncAttributeMaxDynamicSharedMemorySize, S2_SMEM);
    cudaFuncSetAttribute(fused_kernel,  cudaFuncAttributeMaxDynamicSharedMemorySize, S2_SMEM);

    prep_w1_kernel<<<64, 256>>>(W1);
    prep_w2_kernel<<<64, 256>>>(W2);

    // 8-slab software pipeline: overlap stage2(slab s) with stage1(slab s+1).
    stage1_kernel<<<dim3(64, SLAB / 128, 2), 256, S1_SMEM>>>(x, 0);
    for (int s = 0; s < 7; s++)
        fused_kernel<<<768, 256, S2_SMEM>>>(x, y, s * SLAB, (s + 1) * SLAB);
    stage2_kernel<<<dim3(64, SLAB / 128), 256, S2_SMEM>>>(y, 7 * SLAB);
}

// round 17
// speedup vs baseline: 1.0740x; 1.0740x over previous
#include <cuda_runtime.h>
#include <cuda_bf16.h>
#include <cstdint>

// BTT layer: B=4096, M1=M2=N1=N2=64, R=4.
//   stage1 (per m2): C[4096x256] = x[:, m2*64:+64] @ W1[m2]   (K=64)
//   stage2 (per n1): y[:, n1*64:+64] = t[n1] @ W2[n1]         (K=256)
// bf16 hi/lo split, 3 combos -> ~6e-6 rel err.
// g_t stores MMA-ready (hi2, lo2) fragment words.
// R17: R15 schedule (1024-row slabs, fused overlap) + dependency-free MMA
//      bursts: all B-plane LDSMs issued up front into separate register arrays
//      (kills the WAR serialization between plane groups).

#define NB 4096
#define SLAB 1024

__device__ uint4 g_t[16777216];     // 256MB
__device__ uint4 g_w1hi[131072];    // [m2][n=256][k-octet=8] (2MB)
__device__ uint4 g_w1lo[131072];
__device__ uint4 g_w2hi[131072];    // [n1][n2=64][k-octet=32] (2MB)
__device__ uint4 g_w2lo[131072];

__device__ __forceinline__ void fsplit2(float e0, float e1, uint32_t& w_hi, uint32_t& w_lo) {
    asm("cvt.rn.bf16x2.f32 %0, %1, %2;" : "=r"(w_hi) : "f"(e1), "f"(e0));
    float h0 = __uint_as_float(w_hi << 16);
    float h1 = __uint_as_float(w_hi & 0xFFFF0000u);
    float r0 = e0 - h0, r1 = e1 - h1;
    asm("cvt.rn.bf16x2.f32 %0, %1, %2;" : "=r"(w_lo) : "f"(r1), "f"(r0));
}
__device__ __forceinline__ void mma16816(float* c, const uint32_t* a, const uint32_t* b) {
    asm volatile("mma.sync.aligned.m16n8k16.row.col.f32.bf16.bf16.f32 "
        "{%0,%1,%2,%3}, {%4,%5,%6,%7}, {%8,%9}, {%0,%1,%2,%3};"
        : "+f"(c[0]), "+f"(c[1]), "+f"(c[2]), "+f"(c[3])
        : "r"(a[0]), "r"(a[1]), "r"(a[2]), "r"(a[3]), "r"(b[0]), "r"(b[1]));
}
__device__ __forceinline__ void ldsm4(uint32_t* r, uint32_t addr) {
    asm volatile("ldmatrix.sync.aligned.m8n8.x4.shared.b16 {%0,%1,%2,%3}, [%4];"
        : "=r"(r[0]), "=r"(r[1]), "=r"(r[2]), "=r"(r[3]) : "r"(addr));
}

#define RS 144

// ---------------- prep kernels ----------------------------------------------
__global__ void prep_w1_kernel(const float* __restrict__ W1) {
    const int m2 = blockIdx.x, n = threadIdx.x;
    const float* Wm = W1 + (size_t)m2 * 16384;
    #pragma unroll
    for (int j = 0; j < 8; j++) {
        uint32_t h[4], l[4];
        #pragma unroll
        for (int q = 0; q < 4; q++)
            fsplit2(Wm[(8 * j + 2 * q) * 256 + n], Wm[(8 * j + 2 * q + 1) * 256 + n], h[q], l[q]);
        const int idx = (m2 * 256 + n) * 8 + j;
        g_w1hi[idx] = make_uint4(h[0], h[1], h[2], h[3]);
        g_w1lo[idx] = make_uint4(l[0], l[1], l[2], l[3]);
    }
}
__global__ void prep_w2_kernel(const float* __restrict__ W2) {
    const int n1 = blockIdx.x, tid = threadIdx.x;
    const int n2 = tid & 63, kq = tid >> 6;
    const float* Wn = W2 + (size_t)n1 * 16384;
    #pragma unroll
    for (int j = 0; j < 8; j++) {
        const int k0 = kq * 64 + j * 8;
        uint32_t h[4], l[4];
        #pragma unroll
        for (int q = 0; q < 4; q++)
            fsplit2(Wn[(k0 + 2 * q) * 64 + n2], Wn[(k0 + 2 * q + 1) * 64 + n2], h[q], l[q]);
        const int idx = (n1 * 64 + n2) * 32 + kq * 8 + j;
        g_w2hi[idx] = make_uint4(h[0], h[1], h[2], h[3]);
        g_w2lo[idx] = make_uint4(l[0], l[1], l[2], l[3]);
    }
}

// ---------------- stage 1 body: tile 128(b) x 128(n), K=64 ------------------
#define S1_BHI 0
#define S1_BLO 18432
#define S1_SMEM 36864

__device__ __forceinline__ void stage1_body(const float* __restrict__ x, int bslab,
                                            int m2, int by, int nz, char* smem) {
    const uint32_t sb = (uint32_t)__cvta_generic_to_shared(smem);
    const int tid = threadIdx.x, wid = tid >> 5, lane = tid & 31;
    const int b0 = bslab + by * 128, nbase = nz * 128;

    {   // B fill
        const uint4* bh = g_w1hi + (m2 * 256 + nbase) * 8;
        const uint4* bl = g_w1lo + (m2 * 256 + nbase) * 8;
        #pragma unroll
        for (int i = 0; i < 4; i++) {
            const int idx = tid + 256 * i;
            const int row = idx >> 3, q = idx & 7;
            *(uint4*)(smem + S1_BHI + row * RS + q * 16) = bh[idx];
            *(uint4*)(smem + S1_BLO + row * RS + q * 16) = bl[idx];
        }
    }
    __syncthreads();

    const int qr = lane >> 2, qc = lane & 3;
    const uint32_t laneB = (uint32_t)(((lane & 7) + ((lane & 16) ? 8 : 0)) * RS +
                                      ((lane & 8) ? 16 : 0));
    const int row0 = b0 + wid * 16 + qr;
    const float* xr0 = x + (size_t)row0 * 4096 + m2 * 64;
    const float* xr1 = xr0 + (size_t)8 * 4096;

    float acc[16][4];
    #pragma unroll
    for (int nt = 0; nt < 16; nt++)
        #pragma unroll
        for (int r = 0; r < 4; r++) acc[nt][r] = 0.f;

    float2 f[4];
    f[0] = *(const float2*)(xr0 + 2 * qc);
    f[1] = *(const float2*)(xr1 + 2 * qc);
    f[2] = *(const float2*)(xr0 + 2 * qc + 8);
    f[3] = *(const float2*)(xr1 + 2 * qc + 8);

    #pragma unroll
    for (int ks = 0; ks < 4; ks++) {
        float2 nf[4];
        if (ks < 3) {
            const int k0 = (ks + 1) * 16 + 2 * qc;
            nf[0] = *(const float2*)(xr0 + k0);
            nf[1] = *(const float2*)(xr1 + k0);
            nf[2] = *(const float2*)(xr0 + k0 + 8);
            nf[3] = *(const float2*)(xr1 + k0 + 8);
        }
        uint32_t ah[4], al[4];
        fsplit2(f[0].x, f[0].y, ah[0], al[0]);
        fsplit2(f[1].x, f[1].y, ah[1], al[1]);
        fsplit2(f[2].x, f[2].y, ah[2], al[2]);
        fsplit2(f[3].x, f[3].y, ah[3], al[3]);

        // All 8 BHI ldsm4 up front -> 32 dependency-free MMAs
        uint32_t b[16][2];
        #pragma unroll
        for (int p = 0; p < 8; p++) {
            uint32_t r[4];
            ldsm4(r, sb + S1_BHI + laneB + p * 16 * RS + ks * 32);
            b[2 * p][0] = r[0]; b[2 * p][1] = r[1];
            b[2 * p + 1][0] = r[2]; b[2 * p + 1][1] = r[3];
        }
        #pragma unroll
        for (int nt = 0; nt < 16; nt++) {
            mma16816(acc[nt], ah, b[nt]);
            mma16816(acc[nt], al, b[nt]);
        }
        // BLO group (single WAR boundary on b)
        #pragma unroll
        for (int p = 0; p < 8; p++) {
            uint32_t r[4];
            ldsm4(r, sb + S1_BLO + laneB + p * 16 * RS + ks * 32);
            b[2 * p][0] = r[0]; b[2 * p][1] = r[1];
            b[2 * p + 1][0] = r[2]; b[2 * p + 1][1] = r[3];
        }
        #pragma unroll
        for (int nt = 0; nt < 16; nt++)
            mma16816(acc[nt], ah, b[nt]);

        if (ks < 3) { f[0] = nf[0]; f[1] = nf[1]; f[2] = nf[2]; f[3] = nf[3]; }
    }

    uint32_t* gt = (uint32_t*)g_t;
    #pragma unroll
    for (int nt = 0; nt < 16; nt++) {
        const int cg = nbase + nt * 8 + qc * 2;
        const size_t base = (((size_t)(cg >> 2) * 64 + m2) * 4096) * 4 + (cg & 3);
        uint32_t whi, wlo;
        fsplit2(acc[nt][0], acc[nt][1], whi, wlo);
        *(uint2*)(gt + base + (size_t)row0 * 4) = make_uint2(whi, wlo);
        fsplit2(acc[nt][2], acc[nt][3], whi, wlo);
        *(uint2*)(gt + base + (size_t)(row0 + 8) * 4) = make_uint2(whi, wlo);
    }
}

// ---------------- stage 2 body: tile 128(b) x 64(n2), K=256 -----------------
#define S2_BHI 0
#define S2_BLO 36864
#define S2_SMEM 73728
#define TA0 0
#define TA1 32
#define TA2 32768
#define TA3 32800
#define TSTEP 65536

__device__ __forceinline__ void stage2_body(float* __restrict__ y, int bslab,
                                            int n1, int by, char* smem) {
    const uint32_t sb = (uint32_t)__cvta_generic_to_shared(smem);
    const int tid = threadIdx.x, wid = tid >> 5, lane = tid & 31;
    const int b0 = bslab + by * 128;

    {   // B fill
        const uint4* bh = g_w2hi + n1 * 2048;
        const uint4* bl = g_w2lo + n1 * 2048;
        #pragma unroll
        for (int i = 0; i < 8; i++) {
            const int idx = tid + 256 * i;
            const int n2 = idx >> 5, w = idx & 31;
            const int chunk = w >> 3, q = w & 7;
            const int dst = chunk * 9216 + n2 * RS + q * 16;
            *(uint4*)(smem + S2_BHI + dst) = bh[idx];
            *(uint4*)(smem + S2_BLO + dst) = bl[idx];
        }
    }
    __syncthreads();

    const int qr = lane >> 2, qc = lane & 3;
    const uint32_t laneB = (uint32_t)(((lane & 7) + ((lane & 16) ? 8 : 0)) * RS +
                                      ((lane & 8) ? 16 : 0));
    const int qch = qc >> 1, rr = (qc & 1) * 2;
    const int row0 = b0 + wid * 16 + qr;

    float acc[8][4];
    #pragma unroll
    for (int nt = 0; nt < 8; nt++)
        #pragma unroll
        for (int r = 0; r < 4; r++) acc[nt][r] = 0.f;

    const uint32_t* tp = (const uint32_t*)g_t + (size_t)n1 * 64 * 16384 +
                         (size_t)qch * 16384 + (size_t)row0 * 4 + rr;

    uint2 cur[4], nx1[4];
    cur[0] = *(const uint2*)(tp + TA0); cur[1] = *(const uint2*)(tp + TA1);
    cur[2] = *(const uint2*)(tp + TA2); cur[3] = *(const uint2*)(tp + TA3);
    tp += TSTEP;
    nx1[0] = *(const uint2*)(tp + TA0); nx1[1] = *(const uint2*)(tp + TA1);
    nx1[2] = *(const uint2*)(tp + TA2); nx1[3] = *(const uint2*)(tp + TA3);

    #pragma unroll
    for (int g = 0; g < 16; g++) {
        uint2 nx2[4];
        if (g < 14) {
            tp += TSTEP;
            nx2[0] = *(const uint2*)(tp + TA0); nx2[1] = *(const uint2*)(tp + TA1);
            nx2[2] = *(const uint2*)(tp + TA2); nx2[3] = *(const uint2*)(tp + TA3);
        }
        uint32_t ah[4] = {cur[0].x, cur[1].x, cur[2].x, cur[3].x};
        uint32_t al[4] = {cur[0].y, cur[1].y, cur[2].y, cur[3].y};

        const int ch = g >> 2, ksl = g & 3;
        // All 8 ldsm4 (both planes) up front -> 24 dependency-free MMAs
        uint32_t bh[8][2], bl[8][2];
        #pragma unroll
        for (int p = 0; p < 4; p++) {
            uint32_t r[4];
            ldsm4(r, sb + S2_BHI + ch * 9216 + laneB + p * 16 * RS + ksl * 32);
            bh[2 * p][0] = r[0]; bh[2 * p][1] = r[1];
            bh[2 * p + 1][0] = r[2]; bh[2 * p + 1][1] = r[3];
        }
        #pragma unroll
        for (int p = 0; p < 4; p++) {
            uint32_t r[4];
            ldsm4(r, sb + S2_BLO + ch * 9216 + laneB + p * 16 * RS + ksl * 32);
            bl[2 * p][0] = r[0]; bl[2 * p][1] = r[1];
            bl[2 * p + 1][0] = r[2]; bl[2 * p + 1][1] = r[3];
        }
        #pragma unroll
        for (int nt = 0; nt < 8; nt++) {
            mma16816(acc[nt], ah, bh[nt]);
            mma16816(acc[nt], al, bh[nt]);
            mma16816(acc[nt], ah, bl[nt]);
        }
        #pragma unroll
        for (int i = 0; i < 4; i++) { cur[i] = nx1[i]; }
        if (g < 14) {
            #pragma unroll
            for (int i = 0; i < 4; i++) { nx1[i] = nx2[i]; }
        }
    }

    #pragma unroll
    for (int nt = 0; nt < 8; nt++) {
        const int col = n1 * 64 + nt * 8 + qc * 2;
        *(float2*)(y + (size_t)row0 * 4096 + col) = make_float2(acc[nt][0], acc[nt][1]);
        *(float2*)(y + (size_t)(row0 + 8) * 4096 + col) = make_float2(acc[nt][2], acc[nt][3]);
    }
}

// ---------------- kernels ----------------------------------------------------
__global__ void __launch_bounds__(256, 2)
stage1_kernel(const float* __restrict__ x, int bslab) {
    extern __shared__ char smem[];
    stage1_body(x, bslab, blockIdx.x, blockIdx.y, blockIdx.z, smem);
}
__global__ void __launch_bounds__(256, 2)
stage2_kernel(float* __restrict__ y, int bslab) {
    extern __shared__ char smem[];
    stage2_body(y, bslab, blockIdx.x, blockIdx.y, smem);
}
// fused: blocks [0,512) = stage2(slab_s2), blocks [512,1536) = stage1(slab_s1)
__global__ void __launch_bounds__(256, 2)
fused_kernel(const float* __restrict__ x, float* __restrict__ y,
             int slab_s2, int slab_s1) {
    extern __shared__ char smem[];
    const int bx = blockIdx.x;
    if (bx < 512) {
        stage2_body(y, slab_s2, bx & 63, bx >> 6, smem);
    } else {
        const int v = bx - 512;
        stage1_body(x, slab_s1, v & 63, (v >> 6) & 7, v >> 9, smem);
    }
}

// ---------------------------------------------------------------------------
extern "C" void kernel_launch(void* const* d_in, const int* in_sizes, int n_in,
                              void* d_out, int out_size) {
    const float* x  = (const float*)d_in[0];
    const float* W1 = (const float*)d_in[1];
    const float* W2 = (const float*)d_in[2];
    float* y = (float*)d_out;

    cudaFuncSetAttribute(stage1_kernel, cudaFuncAttributeMaxDynamicSharedMemorySize, S1_SMEM);
    cudaFuncSetAttribute(stage2_kernel, cudaFuncAttributeMaxDynamicSharedMemorySize, S2_SMEM);
    cudaFuncSetAttribute(fused_kernel,  cudaFuncAttributeMaxDynamicSharedMemorySize, S2_SMEM);

    prep_w1_kernel<<<64, 256>>>(W1);
    prep_w2_kernel<<<64, 256>>>(W2);

    // Software pipeline: overlap stage2(slab s) with stage1(slab s+1).
    stage1_kernel<<<dim3(64, SLAB / 128, 2), 256, S1_SMEM>>>(x, 0);
    for (int s = 0; s < 3; s++)
        fused_kernel<<<1536, 256, S2_SMEM>>>(x, y, s * SLAB, (s + 1) * SLAB);
    stage2_kernel<<<dim3(64, SLAB / 128), 256, S2_SMEM>>>(y, 3 * SLAB);
}